// round 7
// baseline (speedup 1.0000x reference)
#include <cuda_runtime.h>
#include <math.h>

#define IMG_H 1500
#define IMG_W 2000
#define HW    (IMG_H * IMG_W)
#define NUM_V 10
#define NSLOT 32

// ---------------- device scratch (static; no runtime allocation) ----------------
// Quad layout: entry (x,y) = uint4 with the full 2x2 bilinear footprint.
//   .x = pixel(x,y)  .y = pixel(x+1,y)  .z = pixel(x,y+1)  .w = pixel(x+1,y+1)
// Each pixel packs r/g/b as 10-bit fixed point: (r<<20)|(g<<10)|b.
__device__ uint4 g_img1[HW];   // 48 MB
__device__ uint4 g_img2[HW];   // 48 MB
__device__ double g_sim[NSLOT];
__device__ double g_nrm[NSLOT];
__device__ double g_nz[NSLOT];
__device__ unsigned long long g_cnt[NSLOT];
__device__ float  g_T[12];     // rows 0..2 of K2h @ E2 @ inv(E1)
__device__ unsigned int g_done;

// ---------------- init (separate kernel: keeps double math OUT of k_pack) -------
__global__ void k_init(const float* __restrict__ K2,
                       const float* __restrict__ E1,
                       const float* __restrict__ E2) {
    int t = threadIdx.x;
    if (t < NSLOT) { g_sim[t] = 0.0; g_nrm[t] = 0.0; g_nz[t] = 0.0; g_cnt[t] = 0ull; }
    if (t == 0) {
        g_done = 0u;
        double a[4][8];
        for (int i = 0; i < 4; i++)
            for (int j = 0; j < 4; j++) {
                a[i][j] = (double)E1[i * 4 + j];
                a[i][4 + j] = (i == j) ? 1.0 : 0.0;
            }
        for (int c = 0; c < 4; c++) {
            int p = c; double mx = fabs(a[c][c]);
            for (int r = c + 1; r < 4; r++) {
                double v = fabs(a[r][c]);
                if (v > mx) { mx = v; p = r; }
            }
            if (p != c)
                for (int j = 0; j < 8; j++) { double tmp = a[c][j]; a[c][j] = a[p][j]; a[p][j] = tmp; }
            double pv = a[c][c];
            for (int j = 0; j < 8; j++) a[c][j] /= pv;
            for (int r = 0; r < 4; r++)
                if (r != c) {
                    double f = a[r][c];
                    for (int j = 0; j < 8; j++) a[r][j] -= f * a[c][j];
                }
        }
        double M[4][4];
        for (int i = 0; i < 4; i++)
            for (int j = 0; j < 4; j++) {
                double s = 0.0;
                for (int k = 0; k < 4; k++) s += (double)E2[i * 4 + k] * a[k][4 + j];
                M[i][j] = s;
            }
        for (int r = 0; r < 3; r++)
            for (int j = 0; j < 4; j++) {
                double s = 0.0;
                for (int k = 0; k < 3; k++) s += (double)K2[r * 3 + k] * M[k][j];
                g_T[r * 4 + j] = (float)s;
            }
    }
}

__device__ __forceinline__ unsigned int pack10(float r, float g, float b) {
    unsigned int qr = min(1023u, __float2uint_rn(r * 1023.0f));
    unsigned int qg = min(1023u, __float2uint_rn(g * 1023.0f));
    unsigned int qb = min(1023u, __float2uint_rn(b * 1023.0f));
    return (qr << 20) | (qg << 10) | qb;
}

// ---------------- pack: 4 quad entries per thread, vectorized reads -------------
// W = 2000 is divisible by 4, so a 4-entry group never crosses a row boundary.
__global__ void __launch_bounds__(256) k_pack(const float* __restrict__ r1,
                                              const float* __restrict__ r2) {
    const int groups = HW / 4;
    int tid = blockIdx.x * blockDim.x + threadIdx.x;
    if (tid >= 2 * groups) return;

    const float* src;
    uint4* dst;
    int g;
    if (tid < groups) { src = r1; dst = g_img1; g = tid; }
    else              { src = r2; dst = g_img2; g = tid - groups; }

    int base = g * 4;                    // linear index of first entry
    int y  = base / IMG_W;
    int x4 = base - y * IMG_W;
    int row0 = y * IMG_W;
    int row1 = (y + 1 < IMG_H ? y + 1 : IMG_H - 1) * IMG_W;
    int xe = (x4 + 4 < IMG_W) ? x4 + 4 : IMG_W - 1;   // clamped 5th pixel

    float pix[3][2][5];
#pragma unroll
    for (int c = 0; c < 3; c++) {
        const float* pc = src + c * HW;
        float4 a0 = *reinterpret_cast<const float4*>(pc + row0 + x4);
        float4 a1 = *reinterpret_cast<const float4*>(pc + row1 + x4);
        pix[c][0][0] = a0.x; pix[c][0][1] = a0.y; pix[c][0][2] = a0.z; pix[c][0][3] = a0.w;
        pix[c][1][0] = a1.x; pix[c][1][1] = a1.y; pix[c][1][2] = a1.z; pix[c][1][3] = a1.w;
        pix[c][0][4] = pc[row0 + xe];
        pix[c][1][4] = pc[row1 + xe];
    }

    unsigned int pk[2][5];
#pragma unroll
    for (int r = 0; r < 2; r++)
#pragma unroll
        for (int i = 0; i < 5; i++)
            pk[r][i] = pack10(pix[0][r][i], pix[1][r][i], pix[2][r][i]);

#pragma unroll
    for (int e = 0; e < 4; e++) {
        uint4 v;
        v.x = pk[0][e]; v.y = pk[0][e + 1];
        v.z = pk[1][e]; v.w = pk[1][e + 1];
        dst[base + e] = v;
    }
}

// ---------------- bilinear sample: ONE LDG.128 per sample ----------------
__device__ __forceinline__ float3 bilerp(const uint4* __restrict__ im, float uu, float vv) {
    float x = uu * (float)(IMG_W - 1);
    float y = vv * (float)(IMG_H - 1);
    float fx = floorf(x), fy = floorf(y);
    float wx = x - fx, wy = y - fy;
    int b = (int)fy * IMG_W + (int)fx;        // fx<=W-2, fy<=H-2 guaranteed by clip

    uint4 q = __ldg(im + b);

    const float s = 1.0f / 1023.0f;
    float w00 = (1.0f - wx) * (1.0f - wy) * s;
    float w01 = wx * (1.0f - wy) * s;
    float w10 = (1.0f - wx) * wy * s;
    float w11 = wx * wy * s;

    float3 r;
    r.x = w00 * (float)(q.x >> 20)
        + w01 * (float)(q.y >> 20)
        + w10 * (float)(q.z >> 20)
        + w11 * (float)(q.w >> 20);
    r.y = w00 * (float)((q.x >> 10) & 1023u)
        + w01 * (float)((q.y >> 10) & 1023u)
        + w10 * (float)((q.z >> 10) & 1023u)
        + w11 * (float)((q.w >> 10) & 1023u);
    r.z = w00 * (float)(q.x & 1023u)
        + w01 * (float)(q.y & 1023u)
        + w10 * (float)(q.z & 1023u)
        + w11 * (float)(q.w & 1023u);
    return r;
}

// ------ per-edge prep + sampling + all losses + last-block finalize -------------
__global__ void __launch_bounds__(128) k_sample(const float* __restrict__ ep,
                                                const float* __restrict__ K1g,
                                                float* __restrict__ out) {
    int e = blockIdx.x;
    const float* pe = ep + (size_t)e * 12;
    float p0x = pe[0],  p0y = pe[1],  p0z = pe[2];
    float p1x = pe[3],  p1y = pe[4],  p1z = pe[5];
    float p2x = pe[6],  p2y = pe[7],  p2z = pe[8];
    float p3x = pe[9],  p3y = pe[10], p3z = pe[11];

    float cdx = p1x - p0x, cdy = p1y - p0y, cdz = p1z - p0z;
    float ax = cdx + 1e-6f, ay = cdy + 1e-6f, az = cdz + 1e-6f;
    float clen = sqrtf(ax * ax + ay * ay + az * az);

    int numh = (int)floorf(clen / 0.05f);
    numh = numh < 2 ? 2 : (numh > 1000 ? 1000 : numh);

    float dx = cdx / clen, dy = cdy / clen, dz = cdz / clen;
    float nxd = p3x - p1x, nyd = p3y - p1y, nzd = p3z - p1z;

    float cnx = dy * nzd - dz * nyd;
    float cny = dz * nxd - dx * nzd;
    float cnz = dx * nyd - dy * nxd;
    float nn = sqrtf(cnx * cnx + cny * cny + cnz * cnz) + 1e-6f;
    cnx /= nn; cny /= nn; cnz /= nn;
    if (cnz > 0.0f) { cnx = -cnx; cny = -cny; cnz = -cnz; }

    float ux = cny * dz - cnz * dy;
    float uy = cnz * dx - cnx * dz;
    float uz = cnx * dy - cny * dx;
    float un = sqrtf(ux * ux + uy * uy + uz * uz) + 1e-6f;
    ux /= un; uy /= un; uz /= un;

    if (threadIdx.x == 0) {
        float pxd = p0x - p2x, pyd = p0y - p2y, pzd = p0z - p2z;
        float pnx = pyd * dz - pzd * dy;
        float pny = pzd * dx - pxd * dz;
        float pnz = pxd * dy - pyd * dx;
        float pn = sqrtf(pnx * pnx + pny * pny + pnz * pnz) + 1e-6f;
        float nterm = 1.0f - (cnx * pnx + cny * pny + cnz * pnz) / pn;

        float ox = p0y * p1z - p0z * p1y;
        float oy = p0z * p1x - p0x * p1z;
        float oz = p0x * p1y - p0y * p1x;
        float on = sqrtf(ox * ox + oy * oy + oz * oz) + 1e-6f;
        float snp = fminf(fabsf((ux * ox + uy * oy + uz * oz) / on), 0.5f);
        float zterm = 1.0f - snp * 2.0f;

        int slot = e & (NSLOT - 1);
        atomicAdd(&g_nrm[slot], (double)nterm);
        atomicAdd(&g_nz[slot], (double)zterm);
        atomicAdd(&g_cnt[slot], (unsigned long long)numh);
    }

    float K0 = __ldg(K1g + 0), K1 = __ldg(K1g + 1), K2 = __ldg(K1g + 2);
    float K3 = __ldg(K1g + 3), K4 = __ldg(K1g + 4), K5 = __ldg(K1g + 5);
    float K6 = __ldg(K1g + 6), K7 = __ldg(K1g + 7), K8 = __ldg(K1g + 8);
    float T[12];
#pragma unroll
    for (int j = 0; j < 12; j++) T[j] = g_T[j];

    int total = numh * NUM_V;
    float inv_denom = 1.0f / (float)(numh - 1);
    const float inv9h = (1.0f / 9.0f) * 0.5f;
    float lsum = 0.0f;

    for (int t = threadIdx.x; t < total; t += 128) {
        int ix = t / NUM_V;
        int dv = t - ix * NUM_V;
        float cx = ((float)ix * inv_denom) * clen;
        float cy = (float)dv * inv9h;
        float px = fmaf(dx, cx, fmaf(ux, cy, p0x));
        float py = fmaf(dy, cx, fmaf(uy, cy, p0y));
        float pz = fmaf(dz, cx, fmaf(uz, cy, p0z));

        float u1 = K0 * px + K1 * py + K2 * pz;
        float v1 = K3 * px + K4 * py + K5 * pz;
        float w1 = K6 * px + K7 * py + K8 * pz;
        float iw1 = 1.0f / w1;
        float uu1 = fminf(fmaxf(u1 * iw1, 0.0f), 0.999999f);
        float vv1 = fminf(fmaxf(v1 * iw1, 0.0f), 0.999999f);

        float u2 = fmaf(T[0], px, fmaf(T[1], py, fmaf(T[2], pz, T[3])));
        float v2 = fmaf(T[4], px, fmaf(T[5], py, fmaf(T[6], pz, T[7])));
        float w2 = fmaf(T[8], px, fmaf(T[9], py, fmaf(T[10], pz, T[11])));
        float iw2 = 1.0f / w2;
        float uu2 = fminf(fmaxf(u2 * iw2, 0.0f), 0.999999f);
        float vv2 = fminf(fmaxf(v2 * iw2, 0.0f), 0.999999f);

        float3 s1 = bilerp(g_img1, uu1, vv1);
        float3 s2 = bilerp(g_img2, uu2, vv2);
        float d0 = s1.x - s2.x, d1 = s1.y - s2.y, d2 = s1.z - s2.z;
        lsum = fmaf(d0, d0, fmaf(d1, d1, fmaf(d2, d2, lsum)));
    }

#pragma unroll
    for (int o = 16; o > 0; o >>= 1) lsum += __shfl_down_sync(0xffffffffu, lsum, o);
    __shared__ float ws[4];
    __shared__ unsigned int s_ticket;
    int lane = threadIdx.x & 31, w = threadIdx.x >> 5;
    if (lane == 0) ws[w] = lsum;
    __syncthreads();
    if (threadIdx.x == 0) {
        float s = ws[0] + ws[1] + ws[2] + ws[3];
        atomicAdd(&g_sim[e & (NSLOT - 1)], (double)s);
        __threadfence();
        s_ticket = atomicAdd(&g_done, 1u);
    }
    __syncthreads();

    // last block to finish performs the final reduction (replaces k_final)
    if (s_ticket == gridDim.x - 1 && threadIdx.x < 32) {
        __threadfence();
        int t = threadIdx.x;
        double sim = __ldcg(&g_sim[t]);
        double nrm = __ldcg(&g_nrm[t]);
        double nz  = __ldcg(&g_nz[t]);
        unsigned long long cnt = __ldcg(&g_cnt[t]);
#pragma unroll
        for (int o = 16; o > 0; o >>= 1) {
            sim += __shfl_down_sync(0xffffffffu, sim, o);
            nrm += __shfl_down_sync(0xffffffffu, nrm, o);
            nz  += __shfl_down_sync(0xffffffffu, nz,  o);
            cnt += __shfl_down_sync(0xffffffffu, cnt, o);
        }
        if (t == 0) {
            double npts = (double)cnt * (double)NUM_V;
            double Nd = (double)gridDim.x;
            out[0] = (float)(sim / (npts * 3.0));
            out[1] = (float)(nrm / (2.0 * Nd));
            out[2] = (float)(nz / Nd);
        }
    }
}

// ---------------- launch ----------------
extern "C" void kernel_launch(void* const* d_in, const int* in_sizes, int n_in,
                              void* d_out, int out_size) {
    const float* ep   = (const float*)d_in[0];
    const float* K1   = (const float*)d_in[1];
    const float* K2   = (const float*)d_in[2];
    const float* E1   = (const float*)d_in[3];
    const float* E2   = (const float*)d_in[4];
    const float* rgb1 = (const float*)d_in[5];
    const float* rgb2 = (const float*)d_in[6];

    int N = in_sizes[0] / 12;

    k_init<<<1, 32>>>(K2, E1, E2);
    int groups2 = 2 * (HW / 4);
    k_pack<<<(groups2 + 255) / 256, 256>>>(rgb1, rgb2);
    k_sample<<<N, 128>>>(ep, K1, (float*)d_out);
}

// round 8
// speedup vs baseline: 1.3523x; 1.3523x over previous
#include <cuda_runtime.h>
#include <math.h>

#define IMG_H 1500
#define IMG_W 2000
#define HW    (IMG_H * IMG_W)
#define NUM_V 10
#define NSLOT 32

// ---------------- device scratch (static; no runtime allocation) ----------------
// Quad layout: entry (x,y) = uint4 with the full 2x2 bilinear footprint.
//   .x = pixel(x,y)  .y = pixel(x+1,y)  .z = pixel(x,y+1)  .w = pixel(x+1,y+1)
// Each pixel packs r/g/b as 10-bit fixed point: (r<<20)|(g<<10)|b.
__device__ uint4 g_img1[HW];   // 48 MB
__device__ uint4 g_img2[HW];   // 48 MB
__device__ double g_sim[NSLOT];
__device__ double g_nrm[NSLOT];
__device__ double g_nz[NSLOT];
__device__ unsigned long long g_cnt[NSLOT];
__device__ float  g_T[12];     // rows 0..2 of K2h @ E2 @ inv(E1)

// ---------------- init: fp32, parallel prefetch, fast -----------------------
__global__ void k_init(const float* __restrict__ K2,
                       const float* __restrict__ E1,
                       const float* __restrict__ E2) {
    __shared__ float sE1[16], sE2[16], sK2[9];
    int t = threadIdx.x;
    // parallel prefetch: one memory round-trip instead of a serial walk
    if (t < 16) sE1[t] = E1[t];
    if (t < 16) sE2[t] = E2[t];
    if (t < 9)  sK2[t] = K2[t];
    if (t < NSLOT) { g_sim[t] = 0.0; g_nrm[t] = 0.0; g_nz[t] = 0.0; g_cnt[t] = 0ull; }
    __syncthreads();

    if (t == 0) {
        // fp32 Gauss-Jordan with partial pivoting (fast RCP divides)
        float a[4][8];
        for (int i = 0; i < 4; i++)
            for (int j = 0; j < 4; j++) {
                a[i][j] = sE1[i * 4 + j];
                a[i][4 + j] = (i == j) ? 1.0f : 0.0f;
            }
        for (int c = 0; c < 4; c++) {
            int p = c; float mx = fabsf(a[c][c]);
            for (int r = c + 1; r < 4; r++) {
                float v = fabsf(a[r][c]);
                if (v > mx) { mx = v; p = r; }
            }
            if (p != c)
                for (int j = 0; j < 8; j++) { float tmp = a[c][j]; a[c][j] = a[p][j]; a[p][j] = tmp; }
            float ipv = 1.0f / a[c][c];
            for (int j = 0; j < 8; j++) a[c][j] *= ipv;
            for (int r = 0; r < 4; r++)
                if (r != c) {
                    float f = a[r][c];
                    for (int j = 0; j < 8; j++) a[r][j] = fmaf(-f, a[c][j], a[r][j]);
                }
        }
        float M[4][4];
        for (int i = 0; i < 4; i++)
            for (int j = 0; j < 4; j++) {
                float s = 0.0f;
                for (int k = 0; k < 4; k++) s = fmaf(sE2[i * 4 + k], a[k][4 + j], s);
                M[i][j] = s;
            }
        for (int r = 0; r < 3; r++)
            for (int j = 0; j < 4; j++) {
                float s = 0.0f;
                for (int k = 0; k < 3; k++) s = fmaf(sK2[r * 3 + k], M[k][j], s);
                g_T[r * 4 + j] = s;
            }
    }
}

__device__ __forceinline__ unsigned int pack10(float r, float g, float b) {
    unsigned int qr = min(1023u, __float2uint_rn(r * 1023.0f));
    unsigned int qg = min(1023u, __float2uint_rn(g * 1023.0f));
    unsigned int qb = min(1023u, __float2uint_rn(b * 1023.0f));
    return (qr << 20) | (qg << 10) | qb;
}

// ---------------- pack both planar images -> 2x2 quad entries -------------------
__global__ void __launch_bounds__(256) k_pack(const float* __restrict__ r1,
                                              const float* __restrict__ r2) {
    int i = blockIdx.x * blockDim.x + threadIdx.x;
    if (i >= 2 * HW) return;
    const float* src = (i < HW) ? r1 : r2;
    uint4* dst       = (i < HW) ? g_img1 : g_img2;
    int j = (i < HW) ? i : i - HW;
    int x = j % IMG_W, y = j / IMG_W;
    int x1 = x + 1 < IMG_W ? x + 1 : IMG_W - 1;
    int y1 = y + 1 < IMG_H ? y + 1 : IMG_H - 1;

    int i00 = y * IMG_W + x,   i01 = y * IMG_W + x1;
    int i10 = y1 * IMG_W + x,  i11 = y1 * IMG_W + x1;

    uint4 v;
    v.x = pack10(src[i00], src[i00 + HW], src[i00 + 2 * HW]);
    v.y = pack10(src[i01], src[i01 + HW], src[i01 + 2 * HW]);
    v.z = pack10(src[i10], src[i10 + HW], src[i10 + 2 * HW]);
    v.w = pack10(src[i11], src[i11 + HW], src[i11 + 2 * HW]);
    dst[j] = v;
}

// ---------------- bilinear sample: ONE LDG.128 per sample ----------------
__device__ __forceinline__ float3 bilerp(const uint4* __restrict__ im, float uu, float vv) {
    float x = uu * (float)(IMG_W - 1);
    float y = vv * (float)(IMG_H - 1);
    float fx = floorf(x), fy = floorf(y);
    float wx = x - fx, wy = y - fy;
    int b = (int)fy * IMG_W + (int)fx;        // fx<=W-2, fy<=H-2 guaranteed by clip

    uint4 q = __ldg(im + b);

    const float s = 1.0f / 1023.0f;
    float w00 = (1.0f - wx) * (1.0f - wy) * s;
    float w01 = wx * (1.0f - wy) * s;
    float w10 = (1.0f - wx) * wy * s;
    float w11 = wx * wy * s;

    float3 r;
    r.x = w00 * (float)(q.x >> 20)
        + w01 * (float)(q.y >> 20)
        + w10 * (float)(q.z >> 20)
        + w11 * (float)(q.w >> 20);
    r.y = w00 * (float)((q.x >> 10) & 1023u)
        + w01 * (float)((q.y >> 10) & 1023u)
        + w10 * (float)((q.z >> 10) & 1023u)
        + w11 * (float)((q.w >> 10) & 1023u);
    r.z = w00 * (float)(q.x & 1023u)
        + w01 * (float)(q.y & 1023u)
        + w10 * (float)(q.z & 1023u)
        + w11 * (float)(q.w & 1023u);
    return r;
}

// ---------------- per-edge prep + sampling + all losses (1 block per edge) -------
__global__ void __launch_bounds__(128) k_sample(const float* __restrict__ ep,
                                                const float* __restrict__ K1g) {
    int e = blockIdx.x;
    const float* pe = ep + (size_t)e * 12;
    float p0x = pe[0],  p0y = pe[1],  p0z = pe[2];
    float p1x = pe[3],  p1y = pe[4],  p1z = pe[5];
    float p2x = pe[6],  p2y = pe[7],  p2z = pe[8];
    float p3x = pe[9],  p3y = pe[10], p3z = pe[11];

    float cdx = p1x - p0x, cdy = p1y - p0y, cdz = p1z - p0z;
    float ax = cdx + 1e-6f, ay = cdy + 1e-6f, az = cdz + 1e-6f;
    float clen = sqrtf(ax * ax + ay * ay + az * az);

    int numh = (int)floorf(clen / 0.05f);
    numh = numh < 2 ? 2 : (numh > 1000 ? 1000 : numh);

    float dx = cdx / clen, dy = cdy / clen, dz = cdz / clen;
    float nxd = p3x - p1x, nyd = p3y - p1y, nzd = p3z - p1z;

    float cnx = dy * nzd - dz * nyd;
    float cny = dz * nxd - dx * nzd;
    float cnz = dx * nyd - dy * nxd;
    float nn = sqrtf(cnx * cnx + cny * cny + cnz * cnz) + 1e-6f;
    cnx /= nn; cny /= nn; cnz /= nn;
    if (cnz > 0.0f) { cnx = -cnx; cny = -cny; cnz = -cnz; }

    float ux = cny * dz - cnz * dy;
    float uy = cnz * dx - cnx * dz;
    float uz = cnx * dy - cny * dx;
    float un = sqrtf(ux * ux + uy * uy + uz * uz) + 1e-6f;
    ux /= un; uy /= un; uz /= un;

    if (threadIdx.x == 0) {
        float pxd = p0x - p2x, pyd = p0y - p2y, pzd = p0z - p2z;
        float pnx = pyd * dz - pzd * dy;
        float pny = pzd * dx - pxd * dz;
        float pnz = pxd * dy - pyd * dx;
        float pn = sqrtf(pnx * pnx + pny * pny + pnz * pnz) + 1e-6f;
        float nterm = 1.0f - (cnx * pnx + cny * pny + cnz * pnz) / pn;

        float ox = p0y * p1z - p0z * p1y;
        float oy = p0z * p1x - p0x * p1z;
        float oz = p0x * p1y - p0y * p1x;
        float on = sqrtf(ox * ox + oy * oy + oz * oz) + 1e-6f;
        float snp = fminf(fabsf((ux * ox + uy * oy + uz * oz) / on), 0.5f);
        float zterm = 1.0f - snp * 2.0f;

        int slot = e & (NSLOT - 1);
        atomicAdd(&g_nrm[slot], (double)nterm);
        atomicAdd(&g_nz[slot], (double)zterm);
        atomicAdd(&g_cnt[slot], (unsigned long long)numh);
    }

    float K0 = __ldg(K1g + 0), K1 = __ldg(K1g + 1), K2 = __ldg(K1g + 2);
    float K3 = __ldg(K1g + 3), K4 = __ldg(K1g + 4), K5 = __ldg(K1g + 5);
    float K6 = __ldg(K1g + 6), K7 = __ldg(K1g + 7), K8 = __ldg(K1g + 8);
    float T[12];
#pragma unroll
    for (int j = 0; j < 12; j++) T[j] = g_T[j];

    int total = numh * NUM_V;
    float inv_denom = 1.0f / (float)(numh - 1);
    const float inv9h = (1.0f / 9.0f) * 0.5f;
    float lsum = 0.0f;

    for (int t = threadIdx.x; t < total; t += 128) {
        int ix = t / NUM_V;
        int dv = t - ix * NUM_V;
        float cx = ((float)ix * inv_denom) * clen;
        float cy = (float)dv * inv9h;
        float px = fmaf(dx, cx, fmaf(ux, cy, p0x));
        float py = fmaf(dy, cx, fmaf(uy, cy, p0y));
        float pz = fmaf(dz, cx, fmaf(uz, cy, p0z));

        float u1 = K0 * px + K1 * py + K2 * pz;
        float v1 = K3 * px + K4 * py + K5 * pz;
        float w1 = K6 * px + K7 * py + K8 * pz;
        float iw1 = 1.0f / w1;
        float uu1 = fminf(fmaxf(u1 * iw1, 0.0f), 0.999999f);
        float vv1 = fminf(fmaxf(v1 * iw1, 0.0f), 0.999999f);

        float u2 = fmaf(T[0], px, fmaf(T[1], py, fmaf(T[2], pz, T[3])));
        float v2 = fmaf(T[4], px, fmaf(T[5], py, fmaf(T[6], pz, T[7])));
        float w2 = fmaf(T[8], px, fmaf(T[9], py, fmaf(T[10], pz, T[11])));
        float iw2 = 1.0f / w2;
        float uu2 = fminf(fmaxf(u2 * iw2, 0.0f), 0.999999f);
        float vv2 = fminf(fmaxf(v2 * iw2, 0.0f), 0.999999f);

        float3 s1 = bilerp(g_img1, uu1, vv1);
        float3 s2 = bilerp(g_img2, uu2, vv2);
        float d0 = s1.x - s2.x, d1 = s1.y - s2.y, d2 = s1.z - s2.z;
        lsum = fmaf(d0, d0, fmaf(d1, d1, fmaf(d2, d2, lsum)));
    }

#pragma unroll
    for (int o = 16; o > 0; o >>= 1) lsum += __shfl_down_sync(0xffffffffu, lsum, o);
    __shared__ float ws[4];
    int lane = threadIdx.x & 31, w = threadIdx.x >> 5;
    if (lane == 0) ws[w] = lsum;
    __syncthreads();
    if (threadIdx.x == 0) {
        float s = ws[0] + ws[1] + ws[2] + ws[3];
        atomicAdd(&g_sim[e & (NSLOT - 1)], (double)s);
    }
}

// ---------------- finalize (parallel: 32 threads, shuffle reduce) ----------------
__global__ void k_final(float* __restrict__ out, int N) {
    int t = threadIdx.x;
    double sim = g_sim[t], nrm = g_nrm[t], nz = g_nz[t];
    unsigned long long cnt = g_cnt[t];
#pragma unroll
    for (int o = 16; o > 0; o >>= 1) {
        sim += __shfl_down_sync(0xffffffffu, sim, o);
        nrm += __shfl_down_sync(0xffffffffu, nrm, o);
        nz  += __shfl_down_sync(0xffffffffu, nz,  o);
        cnt += __shfl_down_sync(0xffffffffu, cnt, o);
    }
    if (t == 0) {
        double npts = (double)cnt * (double)NUM_V;
        out[0] = (float)(sim / (npts * 3.0));
        out[1] = (float)(nrm / (2.0 * (double)N));
        out[2] = (float)(nz / (double)N);
    }
}

// ---------------- launch ----------------
extern "C" void kernel_launch(void* const* d_in, const int* in_sizes, int n_in,
                              void* d_out, int out_size) {
    const float* ep   = (const float*)d_in[0];
    const float* K1   = (const float*)d_in[1];
    const float* K2   = (const float*)d_in[2];
    const float* E1   = (const float*)d_in[3];
    const float* E2   = (const float*)d_in[4];
    const float* rgb1 = (const float*)d_in[5];
    const float* rgb2 = (const float*)d_in[6];

    int N = in_sizes[0] / 12;

    k_init<<<1, 32>>>(K2, E1, E2);
    k_pack<<<(2 * HW + 255) / 256, 256>>>(rgb1, rgb2);
    k_sample<<<N, 128>>>(ep, K1);
    k_final<<<1, 32>>>((float*)d_out, N);
}

// round 9
// speedup vs baseline: 1.3631x; 1.0080x over previous
#include <cuda_runtime.h>
#include <math.h>

#define IMG_H 1500
#define IMG_W 2000
#define HW    (IMG_H * IMG_W)
#define NUM_V 10
#define NSLOT 32

// ---------------- device scratch (static; no runtime allocation) ----------------
// Quad layout: entry (x,y) = uint4 with the full 2x2 bilinear footprint.
//   .x = pixel(x,y)  .y = pixel(x+1,y)  .z = pixel(x,y+1)  .w = pixel(x+1,y+1)
// Each pixel packs r/g/b as 10-bit fixed point: (r<<20)|(g<<10)|b.
__device__ uint4 g_img1[HW];   // 48 MB
__device__ uint4 g_img2[HW];   // 48 MB
__device__ double g_sim[NSLOT];
__device__ double g_nrm[NSLOT];
__device__ double g_nz[NSLOT];
__device__ unsigned long long g_cnt[NSLOT];
__device__ float  g_T[12];     // rows 0..2 of K2h @ E2 @ inv(E1)

// ---------------- init: fp32, parallel prefetch, fast -----------------------
__global__ void k_init(const float* __restrict__ K2,
                       const float* __restrict__ E1,
                       const float* __restrict__ E2) {
    __shared__ float sE1[16], sE2[16], sK2[9];
    int t = threadIdx.x;
    // parallel prefetch: one memory round-trip instead of a serial walk
    if (t < 16) sE1[t] = E1[t];
    if (t < 16) sE2[t] = E2[t];
    if (t < 9)  sK2[t] = K2[t];
    if (t < NSLOT) { g_sim[t] = 0.0; g_nrm[t] = 0.0; g_nz[t] = 0.0; g_cnt[t] = 0ull; }
    __syncthreads();

    if (t == 0) {
        // fp32 Gauss-Jordan with partial pivoting (fast RCP divides)
        float a[4][8];
        for (int i = 0; i < 4; i++)
            for (int j = 0; j < 4; j++) {
                a[i][j] = sE1[i * 4 + j];
                a[i][4 + j] = (i == j) ? 1.0f : 0.0f;
            }
        for (int c = 0; c < 4; c++) {
            int p = c; float mx = fabsf(a[c][c]);
            for (int r = c + 1; r < 4; r++) {
                float v = fabsf(a[r][c]);
                if (v > mx) { mx = v; p = r; }
            }
            if (p != c)
                for (int j = 0; j < 8; j++) { float tmp = a[c][j]; a[c][j] = a[p][j]; a[p][j] = tmp; }
            float ipv = 1.0f / a[c][c];
            for (int j = 0; j < 8; j++) a[c][j] *= ipv;
            for (int r = 0; r < 4; r++)
                if (r != c) {
                    float f = a[r][c];
                    for (int j = 0; j < 8; j++) a[r][j] = fmaf(-f, a[c][j], a[r][j]);
                }
        }
        float M[4][4];
        for (int i = 0; i < 4; i++)
            for (int j = 0; j < 4; j++) {
                float s = 0.0f;
                for (int k = 0; k < 4; k++) s = fmaf(sE2[i * 4 + k], a[k][4 + j], s);
                M[i][j] = s;
            }
        for (int r = 0; r < 3; r++)
            for (int j = 0; j < 4; j++) {
                float s = 0.0f;
                for (int k = 0; k < 3; k++) s = fmaf(sK2[r * 3 + k], M[k][j], s);
                g_T[r * 4 + j] = s;
            }
    }
}

__device__ __forceinline__ unsigned int pack10(float r, float g, float b) {
    unsigned int qr = min(1023u, __float2uint_rn(r * 1023.0f));
    unsigned int qg = min(1023u, __float2uint_rn(g * 1023.0f));
    unsigned int qb = min(1023u, __float2uint_rn(b * 1023.0f));
    return (qr << 20) | (qg << 10) | qb;
}

// ---------------- pack both planar images -> 2x2 quad entries -------------------
__global__ void __launch_bounds__(256) k_pack(const float* __restrict__ r1,
                                              const float* __restrict__ r2) {
    int i = blockIdx.x * blockDim.x + threadIdx.x;
    if (i >= 2 * HW) return;
    const float* src = (i < HW) ? r1 : r2;
    uint4* dst       = (i < HW) ? g_img1 : g_img2;
    int j = (i < HW) ? i : i - HW;
    int x = j % IMG_W, y = j / IMG_W;
    int x1 = x + 1 < IMG_W ? x + 1 : IMG_W - 1;
    int y1 = y + 1 < IMG_H ? y + 1 : IMG_H - 1;

    int i00 = y * IMG_W + x,   i01 = y * IMG_W + x1;
    int i10 = y1 * IMG_W + x,  i11 = y1 * IMG_W + x1;

    uint4 v;
    v.x = pack10(src[i00], src[i00 + HW], src[i00 + 2 * HW]);
    v.y = pack10(src[i01], src[i01 + HW], src[i01 + 2 * HW]);
    v.z = pack10(src[i10], src[i10 + HW], src[i10 + 2 * HW]);
    v.w = pack10(src[i11], src[i11 + HW], src[i11 + 2 * HW]);
    dst[j] = v;
}

// ---------------- bilinear sample: ONE LDG.128 per sample ----------------
__device__ __forceinline__ float3 bilerp(const uint4* __restrict__ im, float uu, float vv) {
    float x = uu * (float)(IMG_W - 1);
    float y = vv * (float)(IMG_H - 1);
    float fx = floorf(x), fy = floorf(y);
    float wx = x - fx, wy = y - fy;
    int b = (int)fy * IMG_W + (int)fx;        // fx<=W-2, fy<=H-2 guaranteed by clip

    uint4 q = __ldg(im + b);

    const float s = 1.0f / 1023.0f;
    float w00 = (1.0f - wx) * (1.0f - wy) * s;
    float w01 = wx * (1.0f - wy) * s;
    float w10 = (1.0f - wx) * wy * s;
    float w11 = wx * wy * s;

    float3 r;
    r.x = w00 * (float)(q.x >> 20)
        + w01 * (float)(q.y >> 20)
        + w10 * (float)(q.z >> 20)
        + w11 * (float)(q.w >> 20);
    r.y = w00 * (float)((q.x >> 10) & 1023u)
        + w01 * (float)((q.y >> 10) & 1023u)
        + w10 * (float)((q.z >> 10) & 1023u)
        + w11 * (float)((q.w >> 10) & 1023u);
    r.z = w00 * (float)(q.x & 1023u)
        + w01 * (float)(q.y & 1023u)
        + w10 * (float)(q.z & 1023u)
        + w11 * (float)(q.w & 1023u);
    return r;
}

// ---------------- per-edge prep + sampling + all losses (1 block per edge) -------
__global__ void __launch_bounds__(128) k_sample(const float* __restrict__ ep,
                                                const float* __restrict__ K1g) {
    int e = blockIdx.x;
    const float* pe = ep + (size_t)e * 12;
    float p0x = pe[0],  p0y = pe[1],  p0z = pe[2];
    float p1x = pe[3],  p1y = pe[4],  p1z = pe[5];
    float p2x = pe[6],  p2y = pe[7],  p2z = pe[8];
    float p3x = pe[9],  p3y = pe[10], p3z = pe[11];

    float cdx = p1x - p0x, cdy = p1y - p0y, cdz = p1z - p0z;
    float ax = cdx + 1e-6f, ay = cdy + 1e-6f, az = cdz + 1e-6f;
    float clen = sqrtf(ax * ax + ay * ay + az * az);

    int numh = (int)floorf(clen / 0.05f);
    numh = numh < 2 ? 2 : (numh > 1000 ? 1000 : numh);

    float dx = cdx / clen, dy = cdy / clen, dz = cdz / clen;
    float nxd = p3x - p1x, nyd = p3y - p1y, nzd = p3z - p1z;

    float cnx = dy * nzd - dz * nyd;
    float cny = dz * nxd - dx * nzd;
    float cnz = dx * nyd - dy * nxd;
    float nn = sqrtf(cnx * cnx + cny * cny + cnz * cnz) + 1e-6f;
    cnx /= nn; cny /= nn; cnz /= nn;
    if (cnz > 0.0f) { cnx = -cnx; cny = -cny; cnz = -cnz; }

    float ux = cny * dz - cnz * dy;
    float uy = cnz * dx - cnx * dz;
    float uz = cnx * dy - cny * dx;
    float un = sqrtf(ux * ux + uy * uy + uz * uz) + 1e-6f;
    ux /= un; uy /= un; uz /= un;

    if (threadIdx.x == 0) {
        float pxd = p0x - p2x, pyd = p0y - p2y, pzd = p0z - p2z;
        float pnx = pyd * dz - pzd * dy;
        float pny = pzd * dx - pxd * dz;
        float pnz = pxd * dy - pyd * dx;
        float pn = sqrtf(pnx * pnx + pny * pny + pnz * pnz) + 1e-6f;
        float nterm = 1.0f - (cnx * pnx + cny * pny + cnz * pnz) / pn;

        float ox = p0y * p1z - p0z * p1y;
        float oy = p0z * p1x - p0x * p1z;
        float oz = p0x * p1y - p0y * p1x;
        float on = sqrtf(ox * ox + oy * oy + oz * oz) + 1e-6f;
        float snp = fminf(fabsf((ux * ox + uy * oy + uz * oz) / on), 0.5f);
        float zterm = 1.0f - snp * 2.0f;

        int slot = e & (NSLOT - 1);
        atomicAdd(&g_nrm[slot], (double)nterm);
        atomicAdd(&g_nz[slot], (double)zterm);
        atomicAdd(&g_cnt[slot], (unsigned long long)numh);
    }

    float K0 = __ldg(K1g + 0), K1 = __ldg(K1g + 1), K2 = __ldg(K1g + 2);
    float K3 = __ldg(K1g + 3), K4 = __ldg(K1g + 4), K5 = __ldg(K1g + 5);
    float K6 = __ldg(K1g + 6), K7 = __ldg(K1g + 7), K8 = __ldg(K1g + 8);
    float T[12];
#pragma unroll
    for (int j = 0; j < 12; j++) T[j] = g_T[j];

    int total = numh * NUM_V;
    float inv_denom = 1.0f / (float)(numh - 1);
    const float inv9h = (1.0f / 9.0f) * 0.5f;
    float lsum = 0.0f;

    for (int t = threadIdx.x; t < total; t += 128) {
        int ix = t / NUM_V;
        int dv = t - ix * NUM_V;
        float cx = ((float)ix * inv_denom) * clen;
        float cy = (float)dv * inv9h;
        float px = fmaf(dx, cx, fmaf(ux, cy, p0x));
        float py = fmaf(dy, cx, fmaf(uy, cy, p0y));
        float pz = fmaf(dz, cx, fmaf(uz, cy, p0z));

        float u1 = K0 * px + K1 * py + K2 * pz;
        float v1 = K3 * px + K4 * py + K5 * pz;
        float w1 = K6 * px + K7 * py + K8 * pz;
        float iw1 = 1.0f / w1;
        float uu1 = fminf(fmaxf(u1 * iw1, 0.0f), 0.999999f);
        float vv1 = fminf(fmaxf(v1 * iw1, 0.0f), 0.999999f);

        float u2 = fmaf(T[0], px, fmaf(T[1], py, fmaf(T[2], pz, T[3])));
        float v2 = fmaf(T[4], px, fmaf(T[5], py, fmaf(T[6], pz, T[7])));
        float w2 = fmaf(T[8], px, fmaf(T[9], py, fmaf(T[10], pz, T[11])));
        float iw2 = 1.0f / w2;
        float uu2 = fminf(fmaxf(u2 * iw2, 0.0f), 0.999999f);
        float vv2 = fminf(fmaxf(v2 * iw2, 0.0f), 0.999999f);

        float3 s1 = bilerp(g_img1, uu1, vv1);
        float3 s2 = bilerp(g_img2, uu2, vv2);
        float d0 = s1.x - s2.x, d1 = s1.y - s2.y, d2 = s1.z - s2.z;
        lsum = fmaf(d0, d0, fmaf(d1, d1, fmaf(d2, d2, lsum)));
    }

#pragma unroll
    for (int o = 16; o > 0; o >>= 1) lsum += __shfl_down_sync(0xffffffffu, lsum, o);
    __shared__ float ws[4];
    int lane = threadIdx.x & 31, w = threadIdx.x >> 5;
    if (lane == 0) ws[w] = lsum;
    __syncthreads();
    if (threadIdx.x == 0) {
        float s = ws[0] + ws[1] + ws[2] + ws[3];
        atomicAdd(&g_sim[e & (NSLOT - 1)], (double)s);
    }
}

// ---------------- finalize (parallel: 32 threads, shuffle reduce) ----------------
__global__ void k_final(float* __restrict__ out, int N) {
    int t = threadIdx.x;
    double sim = g_sim[t], nrm = g_nrm[t], nz = g_nz[t];
    unsigned long long cnt = g_cnt[t];
#pragma unroll
    for (int o = 16; o > 0; o >>= 1) {
        sim += __shfl_down_sync(0xffffffffu, sim, o);
        nrm += __shfl_down_sync(0xffffffffu, nrm, o);
        nz  += __shfl_down_sync(0xffffffffu, nz,  o);
        cnt += __shfl_down_sync(0xffffffffu, cnt, o);
    }
    if (t == 0) {
        double npts = (double)cnt * (double)NUM_V;
        out[0] = (float)(sim / (npts * 3.0));
        out[1] = (float)(nrm / (2.0 * (double)N));
        out[2] = (float)(nz / (double)N);
    }
}

// ---------------- launch ----------------
extern "C" void kernel_launch(void* const* d_in, const int* in_sizes, int n_in,
                              void* d_out, int out_size) {
    const float* ep   = (const float*)d_in[0];
    const float* K1   = (const float*)d_in[1];
    const float* K2   = (const float*)d_in[2];
    const float* E1   = (const float*)d_in[3];
    const float* E2   = (const float*)d_in[4];
    const float* rgb1 = (const float*)d_in[5];
    const float* rgb2 = (const float*)d_in[6];

    int N = in_sizes[0] / 12;

    k_init<<<1, 32>>>(K2, E1, E2);
    k_pack<<<(2 * HW + 255) / 256, 256>>>(rgb1, rgb2);
    k_sample<<<N, 128>>>(ep, K1);
    k_final<<<1, 32>>>((float*)d_out, N);
}